// round 3
// baseline (speedup 1.0000x reference)
#include <cuda_runtime.h>
#include <cuda_bf16.h>
#include <math_constants.h>

// Problem constants (B=4, S=2048, E=1024), fp32 throughout.
#define EMBED 1024
#define SEQ   2048
#define NBATCH 4

// Scratch (device globals: the allocation-guard-legal scratch path).
__device__ float g_qkv[(long long)NBATCH * SEQ * 3 * EMBED];  // [B,S,3E] ~100.7 MB
__device__ float g_p[(long long)NBATCH * SEQ * SEQ];          // [B,S,S]  ~67.1 MB

// ---------------------------------------------------------------------------
// Tiled SGEMM with register-prefetch + double-buffered smem (1 sync/iter) and
// an N-group threadblock swizzle for L2 locality:
//   C[b] = alpha * A[b] * op(B[b])
//   A: M x K row-major (lda); op(B) = B (K x N, ldb) or B^T (B stored N x K).
//   M, N divisible by 128; K divisible by 16 -> no bounds predication.
// BM=BN=128, BK=16, TM=TN=8, 256 threads.
// ---------------------------------------------------------------------------
#define SWIZZLE_GROUP 16   // N-tiles per raster group

template <int BM, int BN, int BK, int TM, int TN, bool TRANSB>
__global__ __launch_bounds__(256) void sgemm_kernel(
    int M, int N, int K, float alpha,
    const float* __restrict__ Abase, long long strideA, int lda,
    const float* __restrict__ Bbase, long long strideB, int ldb,
    float* __restrict__ Cbase, long long strideC, int ldc)
{
    const float* A = Abase + (long long)blockIdx.z * strideA;
    const float* B = Bbase + (long long)blockIdx.z * strideB;
    float*       C = Cbase + (long long)blockIdx.z * strideC;

    // ---- raster swizzle: linearize (x,y), walk column-groups of
    // SWIZZLE_GROUP N-tiles over all M-tiles before advancing N.
    int cRow, cCol;
    {
        const int nTilesN = gridDim.x;
        const int nTilesM = gridDim.y;
        const int lin     = blockIdx.y * nTilesN + blockIdx.x;
        const int group   = SWIZZLE_GROUP;
        const int tilesPerGroup = group * nTilesM;
        const int g       = lin / tilesPerGroup;        // which N-group
        const int r       = lin % tilesPerGroup;
        const int gw      = min(group, nTilesN - g * group); // width of this group
        cRow = r / gw;
        cCol = g * group + (r % gw);
    }

    __shared__ float As[2][BK][BM];
    __shared__ float Bs[2][BK][BN];

    const int tid  = threadIdx.x;

    // thread tile within the 128x128 block tile: 16x16 threads, each TM x TN
    const int tCol = tid % (BN / TN);   // 0..15
    const int tRow = tid / (BN / TN);   // 0..15

    // K-major loads (A tile; B tile too when TRANSB): float4 along K
    const int kRow    = tid / (BK / 4);        // 0..63
    const int kCol    = (tid % (BK / 4)) * 4;  // {0,4,8,12}
    const int kStride = (256 * 4) / BK;        // 64 rows / iteration -> 2 iters

    // N-major loads (B tile when !TRANSB): float4 along N
    const int nRow    = tid / (BN / 4);        // 0..7
    const int nCol    = (tid % (BN / 4)) * 4;  // 0..124
    const int nStride = (256 * 4) / BN;        // 8 rows / iteration -> 2 iters

    float acc[TM][TN] = {};

    const float* Aptr = A + (long long)cRow * BM * lda;
    const float* Bptr;
    if (TRANSB) Bptr = B + (long long)cCol * BN * ldb;  // B is N x K row-major
    else        Bptr = B + cCol * BN;                   // B is K x N row-major

    // ---- prefetch registers (tile k+1 lives here during compute of tile k)
    float4 pa[2];
    float4 pb[2];

    auto load_tile = [&](int k0) {
        #pragma unroll
        for (int it = 0; it < 2; it++) {
            pa[it] = *reinterpret_cast<const float4*>(
                Aptr + (long long)(kRow + it * kStride) * lda + k0 + kCol);
        }
        if constexpr (TRANSB) {
            #pragma unroll
            for (int it = 0; it < 2; it++) {
                pb[it] = *reinterpret_cast<const float4*>(
                    Bptr + (long long)(kRow + it * kStride) * ldb + k0 + kCol);
            }
        } else {
            #pragma unroll
            for (int it = 0; it < 2; it++) {
                pb[it] = *reinterpret_cast<const float4*>(
                    Bptr + (long long)(k0 + nRow + it * nStride) * ldb + nCol);
            }
        }
    };

    auto store_tile = [&](int buf) {
        #pragma unroll
        for (int it = 0; it < 2; it++) {
            const int r = kRow + it * kStride;
            As[buf][kCol + 0][r] = pa[it].x;
            As[buf][kCol + 1][r] = pa[it].y;
            As[buf][kCol + 2][r] = pa[it].z;
            As[buf][kCol + 3][r] = pa[it].w;
        }
        if constexpr (TRANSB) {
            #pragma unroll
            for (int it = 0; it < 2; it++) {
                const int r = kRow + it * kStride;
                Bs[buf][kCol + 0][r] = pb[it].x;
                Bs[buf][kCol + 1][r] = pb[it].y;
                Bs[buf][kCol + 2][r] = pb[it].z;
                Bs[buf][kCol + 3][r] = pb[it].w;
            }
        } else {
            #pragma unroll
            for (int it = 0; it < 2; it++) {
                *reinterpret_cast<float4*>(&Bs[buf][nRow + it * nStride][nCol]) = pb[it];
            }
        }
    };

    // ---- prologue: fill buffer 0 with tile 0
    load_tile(0);
    store_tile(0);
    __syncthreads();

    int buf = 0;
    for (int k0 = 0; k0 < K; k0 += BK) {
        // issue global loads for the NEXT tile (latency hidden behind compute)
        if (k0 + BK < K) load_tile(k0 + BK);

        // ---- compute from smem[buf] ----
        #pragma unroll
        for (int kk = 0; kk < BK; kk++) {
            float regM[TM], regN[TN];
            float4 m0 = *reinterpret_cast<const float4*>(&As[buf][kk][tRow * TM + 0]);
            float4 m1 = *reinterpret_cast<const float4*>(&As[buf][kk][tRow * TM + 4]);
            regM[0]=m0.x; regM[1]=m0.y; regM[2]=m0.z; regM[3]=m0.w;
            regM[4]=m1.x; regM[5]=m1.y; regM[6]=m1.z; regM[7]=m1.w;
            float4 n0 = *reinterpret_cast<const float4*>(&Bs[buf][kk][tCol * TN + 0]);
            float4 n1 = *reinterpret_cast<const float4*>(&Bs[buf][kk][tCol * TN + 4]);
            regN[0]=n0.x; regN[1]=n0.y; regN[2]=n0.z; regN[3]=n0.w;
            regN[4]=n1.x; regN[5]=n1.y; regN[6]=n1.z; regN[7]=n1.w;
            #pragma unroll
            for (int i = 0; i < TM; i++)
                #pragma unroll
                for (int j = 0; j < TN; j++)
                    acc[i][j] = fmaf(regM[i], regN[j], acc[i][j]);
        }

        // store prefetched tile into the other buffer; ONE sync per iteration.
        if (k0 + BK < K) {
            store_tile(buf ^ 1);
            __syncthreads();
            buf ^= 1;
        }
    }

    // ---- epilogue: C = alpha * acc (vectorized) ----
    #pragma unroll
    for (int i = 0; i < TM; i++) {
        const long long row = (long long)cRow * BM + tRow * TM + i;
        #pragma unroll
        for (int j = 0; j < TN; j += 4) {
            float4 v;
            v.x = alpha * acc[i][j + 0];
            v.y = alpha * acc[i][j + 1];
            v.z = alpha * acc[i][j + 2];
            v.w = alpha * acc[i][j + 3];
            *reinterpret_cast<float4*>(
                C + row * ldc + cCol * BN + tCol * TN + j) = v;
        }
    }
}

// ---------------------------------------------------------------------------
// Row softmax over P: one block per row, cols = SEQ = 2048, 256 threads.
// ---------------------------------------------------------------------------
__inline__ __device__ float warpReduceMax(float v) {
    #pragma unroll
    for (int o = 16; o > 0; o >>= 1) v = fmaxf(v, __shfl_xor_sync(0xFFFFFFFFu, v, o));
    return v;
}
__inline__ __device__ float warpReduceSum(float v) {
    #pragma unroll
    for (int o = 16; o > 0; o >>= 1) v += __shfl_xor_sync(0xFFFFFFFFu, v, o);
    return v;
}

__global__ __launch_bounds__(256) void softmax_rows_kernel(float* __restrict__ P, int cols)
{
    float* p = P + (long long)blockIdx.x * cols;
    const int tid  = threadIdx.x;
    const int lane = tid & 31;
    const int warp = tid >> 5;
    __shared__ float red[8];
    __shared__ float s_stat;

    // cols = 2048, 256 threads -> 8 elements each (2 x float4)
    float4 v0 = reinterpret_cast<const float4*>(p)[tid];
    float4 v1 = reinterpret_cast<const float4*>(p)[tid + 256];

    // ---- max ----
    float m = fmaxf(fmaxf(fmaxf(v0.x, v0.y), fmaxf(v0.z, v0.w)),
                    fmaxf(fmaxf(v1.x, v1.y), fmaxf(v1.z, v1.w)));
    m = warpReduceMax(m);
    if (lane == 0) red[warp] = m;
    __syncthreads();
    if (warp == 0) {
        float t = (lane < 8) ? red[lane] : -CUDART_INF_F;
        t = warpReduceMax(t);
        if (lane == 0) s_stat = t;
    }
    __syncthreads();
    const float rmax = s_stat;

    // ---- exp + sum ----
    v0.x = __expf(v0.x - rmax); v0.y = __expf(v0.y - rmax);
    v0.z = __expf(v0.z - rmax); v0.w = __expf(v0.w - rmax);
    v1.x = __expf(v1.x - rmax); v1.y = __expf(v1.y - rmax);
    v1.z = __expf(v1.z - rmax); v1.w = __expf(v1.w - rmax);
    float s = (v0.x + v0.y + v0.z + v0.w) + (v1.x + v1.y + v1.z + v1.w);
    s = warpReduceSum(s);
    if (lane == 0) red[warp] = s;
    __syncthreads();
    if (warp == 0) {
        float t = (lane < 8) ? red[lane] : 0.0f;
        t = warpReduceSum(t);
        if (lane == 0) s_stat = t;
    }
    __syncthreads();
    const float inv = __frcp_rn(s_stat);

    v0.x *= inv; v0.y *= inv; v0.z *= inv; v0.w *= inv;
    v1.x *= inv; v1.y *= inv; v1.z *= inv; v1.w *= inv;
    reinterpret_cast<float4*>(p)[tid]       = v0;
    reinterpret_cast<float4*>(p)[tid + 256] = v1;
}

// ---------------------------------------------------------------------------
// kernel_launch: 4 graph-capturable launches.
//   1) qkv = hidden @ W_qkv        [8192,1024]x[1024,3072]
//   2) P   = (Q @ K^T) * 1/sqrt(E) [2048x2048 x4, K=1024]
//   3) softmax rows of P
//   4) out = P @ V                 [2048,1024 x4, K=2048]
// ---------------------------------------------------------------------------
extern "C" void kernel_launch(void* const* d_in, const int* in_sizes, int n_in,
                              void* d_out, int out_size)
{
    const float* hidden = (const float*)d_in[0];   // [B, S, E]
    const float* W_qkv  = (const float*)d_in[1];   // [E, 3E]
    float*       out    = (float*)d_out;           // [B, S, E]

    // Resolve scratch symbol addresses once (host-side, capture-safe).
    static float* qkv = nullptr;
    static float* P   = nullptr;
    if (!qkv) {
        cudaGetSymbolAddress((void**)&qkv, g_qkv);
        cudaGetSymbolAddress((void**)&P,   g_p);
    }

    const int  M   = NBATCH * SEQ;     // 8192
    const int  E3  = 3 * EMBED;        // 3072
    const float scale = 1.0f / 32.0f;  // 1/sqrt(1024)
    dim3 block(256);

    // 1) fused QKV projection (batch folded into M)
    sgemm_kernel<128, 128, 16, 8, 8, false>
        <<<dim3(E3 / 128, M / 128, 1), block>>>(
            M, E3, EMBED, 1.0f,
            hidden, 0, EMBED,
            W_qkv,  0, E3,
            qkv,    0, E3);

    // 2) scores = (Q @ K^T) * scale, batched over z
    sgemm_kernel<128, 128, 16, 8, 8, true>
        <<<dim3(SEQ / 128, SEQ / 128, NBATCH), block>>>(
            SEQ, SEQ, EMBED, scale,
            qkv,          (long long)SEQ * E3, E3,   // Q at row offset 0
            qkv + EMBED,  (long long)SEQ * E3, E3,   // K at row offset E
            P,            (long long)SEQ * SEQ, SEQ);

    // 3) row softmax over keys
    softmax_rows_kernel<<<NBATCH * SEQ, block>>>(P, SEQ);

    // 4) out = P @ V, batched over z
    sgemm_kernel<128, 128, 16, 8, 8, false>
        <<<dim3(EMBED / 128, SEQ / 128, NBATCH), block>>>(
            SEQ, EMBED, SEQ, 1.0f,
            P,               (long long)SEQ * SEQ, SEQ,
            qkv + 2 * EMBED, (long long)SEQ * E3,  E3,  // V rows strided by 3E
            out,             (long long)SEQ * EMBED, EMBED);
}

// round 12
// speedup vs baseline: 1.7435x; 1.7435x over previous
#include <cuda_runtime.h>
#include <cuda_bf16.h>
#include <cstdint>
#include <math_constants.h>

// Problem constants (B=4, S=2048, E=1024), fp32 in/out.
#define EMBED  1024
#define SEQ    2048
#define NBATCH 4

// ---------------------------------------------------------------------------
// Device-global scratch (allocation-guard-legal).
// ---------------------------------------------------------------------------
__device__ float g_qkv[(long long)NBATCH * SEQ * 3 * EMBED]; // [B,S,3E]
__device__ float g_p[(long long)NBATCH * SEQ * SEQ];         // [B,S,S]
__device__ float g_wt[(long long)3 * EMBED * EMBED];         // W^T [3E,E]
__device__ float g_vt[(long long)NBATCH * EMBED * SEQ];      // V^T [B][E,S]

// ---------------------------------------------------------------------------
// Portable tensor-core primitives (sm_80+ baseline; assemble for sm_103).
// ---------------------------------------------------------------------------
__device__ __forceinline__ uint32_t smem_u32(const void* p) {
    uint32_t a;
    asm("{ .reg .u64 t; cvta.to.shared.u64 t, %1; cvt.u32.u64 %0, t; }"
        : "=r"(a) : "l"(p));
    return a;
}

__device__ __forceinline__ void ldsm_x4(uint32_t& r0, uint32_t& r1,
                                        uint32_t& r2, uint32_t& r3, uint32_t addr) {
    asm volatile("ldmatrix.sync.aligned.m8n8.x4.shared.b16 {%0,%1,%2,%3}, [%4];"
                 : "=r"(r0), "=r"(r1), "=r"(r2), "=r"(r3) : "r"(addr));
}

// D += A * B  (m16n8k16, bf16 inputs, fp32 accum)
__device__ __forceinline__ void mma_bf16(float* d, const uint32_t* a, const uint32_t* b) {
    asm volatile(
        "mma.sync.aligned.m16n8k16.row.col.f32.bf16.bf16.f32 "
        "{%0,%1,%2,%3}, {%4,%5,%6,%7}, {%8,%9}, {%0,%1,%2,%3};"
        : "+f"(d[0]), "+f"(d[1]), "+f"(d[2]), "+f"(d[3])
        : "r"(a[0]), "r"(a[1]), "r"(a[2]), "r"(a[3]), "r"(b[0]), "r"(b[1]));
}

// split fp32 pair into packed bf16 hi pair + bf16 lo (residual) pair
__device__ __forceinline__ void split2(float a, float b, uint32_t& hi, uint32_t& lo) {
    __nv_bfloat16 ha = __float2bfloat16(a);
    __nv_bfloat16 hb = __float2bfloat16(b);
    __nv_bfloat16 la = __float2bfloat16(a - __bfloat162float(ha));
    __nv_bfloat16 lb = __float2bfloat16(b - __bfloat162float(hb));
    __nv_bfloat162 h2 = __nv_bfloat162(ha, hb);
    __nv_bfloat162 l2 = __nv_bfloat162(la, lb);
    hi = *reinterpret_cast<uint32_t*>(&h2);
    lo = *reinterpret_cast<uint32_t*>(&l2);
}

// ---------------------------------------------------------------------------
// bf16x3 HMMA GEMM: C[z] = alpha * A[z] (M x K fp32, lda) * B[z]^T
//   (B stored N x K fp32, K-major, ldb).
// CTA tile 128x128, K-chunk 32. 8 warps as 4(m) x 2(n), warp tile 32x64.
// Precision: x = hi + lo (bf16); D += Ah*Bh + Ah*Bl + Al*Bh (fp32 accum).
// Smem: 4 tiles of [128][BK+8] bf16 = 40 KB static (conflict-free ldmatrix:
// 80 B row stride => 8 lane-addresses cover distinct banks).
// ---------------------------------------------------------------------------
#define BM 128
#define BN 128
#define BK 32
#define LDT (BK + 8)   // 40 halves = 80 bytes per row

__global__ __launch_bounds__(256) void gemm_mma_kernel(
    int K, float alpha,
    const float* __restrict__ Abase, long long sA, int lda,
    const float* __restrict__ Bbase, long long sB, int ldb,
    float* __restrict__ Cbase, long long sC, int ldc)
{
    __shared__ __align__(16) __nv_bfloat16 sAh[BM * LDT];
    __shared__ __align__(16) __nv_bfloat16 sAl[BM * LDT];
    __shared__ __align__(16) __nv_bfloat16 sBh[BN * LDT];
    __shared__ __align__(16) __nv_bfloat16 sBl[BN * LDT];

    const int tid  = threadIdx.x;
    const int wid  = tid >> 5;
    const int lane = tid & 31;

    const float* A = Abase + (long long)blockIdx.z * sA;
    const float* B = Bbase + (long long)blockIdx.z * sB;
    float*       C = Cbase + (long long)blockIdx.z * sC;
    const int rowBase = blockIdx.y * BM;
    const int colBase = blockIdx.x * BN;

    const int warpM = wid & 3;        // 4 warps over M -> 32 rows each
    const int warpN = wid >> 2;       // 2 warps over N -> 64 cols each
    const int wRow  = warpM * 32;
    const int wCol  = warpN * 64;

    const uint32_t bAh = smem_u32(sAh), bAl = smem_u32(sAl);
    const uint32_t bBh = smem_u32(sBh), bBl = smem_u32(sBl);

    float acc[2][8][4];
    #pragma unroll
    for (int i = 0; i < 2; i++)
        #pragma unroll
        for (int j = 0; j < 8; j++)
            #pragma unroll
            for (int q = 0; q < 4; q++) acc[i][j][q] = 0.0f;

    // ldmatrix lane-address components (half-element indices)
    // A x4: lanes 0-15 -> rows 0..15 @ +0 ; lanes 16-31 -> rows 0..15 @ +8
    const int aLRow = lane & 15;
    const int aLCol = (lane >> 4) * 8;
    // B x4: group g = lane>>3: row = (g>=2 ? 8:0) + (lane&7), col = (g&1)*8
    const int bLRow = ((lane >> 4) ? 8 : 0) + (lane & 7);
    const int bLCol = ((lane >> 3) & 1) * 8;

    for (int k0 = 0; k0 < K; k0 += BK) {
        // ---- fill: fp32 -> bf16 hi/lo tiles (A: 128x32, B: 128x32)
        #pragma unroll
        for (int it = 0; it < 4; it++) {
            const int idx = tid + it * 256;        // 0..1023
            const int r   = idx >> 3;
            const int c4  = (idx & 7) * 4;
            float4 v = *reinterpret_cast<const float4*>(
                A + (long long)(rowBase + r) * lda + k0 + c4);
            uint32_t h0, l0, h1, l1;
            split2(v.x, v.y, h0, l0);
            split2(v.z, v.w, h1, l1);
            *reinterpret_cast<uint2*>(&sAh[r * LDT + c4]) = make_uint2(h0, h1);
            *reinterpret_cast<uint2*>(&sAl[r * LDT + c4]) = make_uint2(l0, l1);
        }
        #pragma unroll
        for (int it = 0; it < 4; it++) {
            const int idx = tid + it * 256;
            const int r   = idx >> 3;
            const int c4  = (idx & 7) * 4;
            float4 v = *reinterpret_cast<const float4*>(
                B + (long long)(colBase + r) * ldb + k0 + c4);
            uint32_t h0, l0, h1, l1;
            split2(v.x, v.y, h0, l0);
            split2(v.z, v.w, h1, l1);
            *reinterpret_cast<uint2*>(&sBh[r * LDT + c4]) = make_uint2(h0, h1);
            *reinterpret_cast<uint2*>(&sBl[r * LDT + c4]) = make_uint2(l0, l1);
        }
        __syncthreads();

        // ---- compute: 2 k16 steps
        #pragma unroll
        for (int ks = 0; ks < 2; ks++) {
            const int kk = ks * 16;

            uint32_t ah[2][4], al[2][4];
            #pragma unroll
            for (int mi = 0; mi < 2; mi++) {
                const uint32_t off =
                    (uint32_t)((wRow + mi * 16 + aLRow) * LDT + kk + aLCol) * 2u;
                ldsm_x4(ah[mi][0], ah[mi][1], ah[mi][2], ah[mi][3], bAh + off);
                ldsm_x4(al[mi][0], al[mi][1], al[mi][2], al[mi][3], bAl + off);
            }

            uint32_t bh[8][2], bl[8][2];
            #pragma unroll
            for (int pi = 0; pi < 4; pi++) {
                const uint32_t off =
                    (uint32_t)((wCol + pi * 16 + bLRow) * LDT + kk + bLCol) * 2u;
                ldsm_x4(bh[2*pi][0], bh[2*pi][1], bh[2*pi+1][0], bh[2*pi+1][1],
                        bBh + off);
                ldsm_x4(bl[2*pi][0], bl[2*pi][1], bl[2*pi+1][0], bl[2*pi+1][1],
                        bBl + off);
            }

            #pragma unroll
            for (int mi = 0; mi < 2; mi++)
                #pragma unroll
                for (int ni = 0; ni < 8; ni++) {
                    mma_bf16(acc[mi][ni], ah[mi], bh[ni]);   // hi*hi
                    mma_bf16(acc[mi][ni], ah[mi], bl[ni]);   // hi*lo
                    mma_bf16(acc[mi][ni], al[mi], bh[ni]);   // lo*hi
                }
        }
        __syncthreads();
    }

    // ---- epilogue: C = alpha * acc
    // fragment layout: d0,d1 -> row t/4,    cols 2*(t%4)+{0,1}
    //                  d2,d3 -> row t/4+8,  same cols
    const int fRow = lane >> 2;
    const int fCol = (lane & 3) * 2;
    #pragma unroll
    for (int mi = 0; mi < 2; mi++) {
        #pragma unroll
        for (int ni = 0; ni < 8; ni++) {
            const long long r0 = rowBase + wRow + mi * 16 + fRow;
            const int c = colBase + wCol + ni * 8 + fCol;
            float2 v0 = make_float2(alpha * acc[mi][ni][0], alpha * acc[mi][ni][1]);
            float2 v1 = make_float2(alpha * acc[mi][ni][2], alpha * acc[mi][ni][3]);
            *reinterpret_cast<float2*>(C + r0 * ldc + c)       = v0;
            *reinterpret_cast<float2*>(C + (r0 + 8) * ldc + c) = v1;
        }
    }
}

// ---------------------------------------------------------------------------
// fp32 tiled transpose: out[x][y] = in[y][x], 32x32 tiles, block (32,8).
// ---------------------------------------------------------------------------
__global__ __launch_bounds__(256) void transpose_kernel(
    const float* __restrict__ in, float* __restrict__ out,
    int ldi, int ldo, long long sIn, long long sOut)
{
    __shared__ float tile[32][33];
    const float* ip = in + (long long)blockIdx.z * sIn;
    float*       op = out + (long long)blockIdx.z * sOut;
    int x  = blockIdx.x * 32 + threadIdx.x;   // input col
    int y0 = blockIdx.y * 32 + threadIdx.y;   // input row
    #pragma unroll
    for (int i = 0; i < 32; i += 8)
        tile[threadIdx.y + i][threadIdx.x] = ip[(long long)(y0 + i) * ldi + x];
    __syncthreads();
    int ox  = blockIdx.y * 32 + threadIdx.x;  // output col (= input row)
    int oy0 = blockIdx.x * 32 + threadIdx.y;  // output row (= input col)
    #pragma unroll
    for (int i = 0; i < 32; i += 8)
        op[(long long)(oy0 + i) * ldo + ox] = tile[threadIdx.x][threadIdx.y + i];
}

// ---------------------------------------------------------------------------
// Row softmax over P (in place, fp32): one block per row, 2048 cols.
// ---------------------------------------------------------------------------
__inline__ __device__ float warpReduceMax(float v) {
    #pragma unroll
    for (int o = 16; o > 0; o >>= 1) v = fmaxf(v, __shfl_xor_sync(0xFFFFFFFFu, v, o));
    return v;
}
__inline__ __device__ float warpReduceSum(float v) {
    #pragma unroll
    for (int o = 16; o > 0; o >>= 1) v += __shfl_xor_sync(0xFFFFFFFFu, v, o);
    return v;
}

__global__ __launch_bounds__(256) void softmax_rows_kernel(float* __restrict__ P, int cols)
{
    float* p = P + (long long)blockIdx.x * cols;
    const int tid = threadIdx.x, lane = tid & 31, warp = tid >> 5;
    __shared__ float red[8];
    __shared__ float s_stat;

    float4 v0 = reinterpret_cast<const float4*>(p)[tid];
    float4 v1 = reinterpret_cast<const float4*>(p)[tid + 256];

    float m = fmaxf(fmaxf(fmaxf(v0.x, v0.y), fmaxf(v0.z, v0.w)),
                    fmaxf(fmaxf(v1.x, v1.y), fmaxf(v1.z, v1.w)));
    m = warpReduceMax(m);
    if (lane == 0) red[warp] = m;
    __syncthreads();
    if (warp == 0) {
        float t = (lane < 8) ? red[lane] : -CUDART_INF_F;
        t = warpReduceMax(t);
        if (lane == 0) s_stat = t;
    }
    __syncthreads();
    const float rmax = s_stat;

    v0.x = __expf(v0.x - rmax); v0.y = __expf(v0.y - rmax);
    v0.z = __expf(v0.z - rmax); v0.w = __expf(v0.w - rmax);
    v1.x = __expf(v1.x - rmax); v1.y = __expf(v1.y - rmax);
    v1.z = __expf(v1.z - rmax); v1.w = __expf(v1.w - rmax);
    float s = (v0.x + v0.y + v0.z + v0.w) + (v1.x + v1.y + v1.z + v1.w);
    s = warpReduceSum(s);
    if (lane == 0) red[warp] = s;
    __syncthreads();
    if (warp == 0) {
        float t = (lane < 8) ? red[lane] : 0.0f;
        t = warpReduceSum(t);
        if (lane == 0) s_stat = t;
    }
    __syncthreads();
    const float inv = __frcp_rn(s_stat);

    v0.x *= inv; v0.y *= inv; v0.z *= inv; v0.w *= inv;
    v1.x *= inv; v1.y *= inv; v1.z *= inv; v1.w *= inv;
    reinterpret_cast<float4*>(p)[tid]       = v0;
    reinterpret_cast<float4*>(p)[tid + 256] = v1;
}

// ---------------------------------------------------------------------------
// kernel_launch: Wt = W^T; qkv = hidden @ W; Vt = V^T;
//                P = (Q K^T)/32; softmax(P); out = P V.
// ---------------------------------------------------------------------------
extern "C" void kernel_launch(void* const* d_in, const int* in_sizes, int n_in,
                              void* d_out, int out_size)
{
    const float* hidden = (const float*)d_in[0];   // [B,S,E]
    const float* W      = (const float*)d_in[1];   // [E,3E]
    float*       out    = (float*)d_out;           // [B,S,E]

    static float *qkv = nullptr, *P = nullptr, *Wt = nullptr, *Vt = nullptr;
    if (!qkv) {
        cudaGetSymbolAddress((void**)&qkv, g_qkv);
        cudaGetSymbolAddress((void**)&P,   g_p);
        cudaGetSymbolAddress((void**)&Wt,  g_wt);
        cudaGetSymbolAddress((void**)&Vt,  g_vt);
    }

    const int E3 = 3 * EMBED;
    dim3 tb(32, 8);

    // 1) Wt[3E,E] = W^T
    transpose_kernel<<<dim3(E3 / 32, EMBED / 32, 1), tb>>>(
        W, Wt, E3, EMBED, 0, 0);

    // 2) qkv = hidden @ W   (M=8192, N=3072, K=1024)
    gemm_mma_kernel<<<dim3(E3 / BN, (NBATCH * SEQ) / BM, 1), 256>>>(
        EMBED, 1.0f,
        hidden, 0, EMBED,
        Wt,     0, EMBED,
        qkv,    0, E3);

    // 3) Vt[b][E,S] = V[b]^T (V = qkv cols 2E..3E)
    transpose_kernel<<<dim3(EMBED / 32, SEQ / 32, NBATCH), tb>>>(
        qkv + 2 * EMBED, Vt, E3, SEQ,
        (long long)SEQ * E3, (long long)EMBED * SEQ);

    // 4) P = (Q @ K^T) / 32   (per batch: M=N=2048, K=1024)
    gemm_mma_kernel<<<dim3(SEQ / BN, SEQ / BM, NBATCH), 256>>>(
        EMBED, 1.0f / 32.0f,
        qkv,          (long long)SEQ * E3, E3,
        qkv + EMBED,  (long long)SEQ * E3, E3,
        P,            (long long)SEQ * SEQ, SEQ);

    // 5) softmax rows
    softmax_rows_kernel<<<NBATCH * SEQ, 256>>>(P, SEQ);

    // 6) out = P @ V = P @ Vt^T   (per batch: M=2048, N=1024, K=2048)
    gemm_mma_kernel<<<dim3(EMBED / BN, SEQ / BM, NBATCH), 256>>>(
        SEQ, 1.0f,
        P,  (long long)SEQ * SEQ, SEQ,
        Vt, (long long)EMBED * SEQ, SEQ,
        out, (long long)SEQ * EMBED, EMBED);
}

// round 14
// speedup vs baseline: 2.2455x; 1.2879x over previous
#include <cuda_runtime.h>
#include <cuda_bf16.h>
#include <cstdint>
#include <math_constants.h>

// Problem constants (B=4, S=2048, E=1024), fp32 in/out.
#define EMBED  1024
#define SEQ    2048
#define NBATCH 4

#define N_HID  ((long long)NBATCH * SEQ * EMBED)        // 8,388,608
#define N_WT   ((long long)3 * EMBED * EMBED)           // 3,145,728
#define N_QKV  ((long long)NBATCH * SEQ * 3 * EMBED)    // 25,165,824
#define N_P    ((long long)NBATCH * SEQ * SEQ)          // 16,777,216
#define N_VT   ((long long)NBATCH * EMBED * SEQ)        // 8,388,608

// ---------------------------------------------------------------------------
// Device-global scratch (allocation-guard-legal).
// ---------------------------------------------------------------------------
__device__ float g_qkv[N_QKV];
__device__ float g_p[N_P];
__device__ float g_wt[N_WT];
__device__ float g_vt[N_VT];
__device__ __align__(16) __nv_bfloat16 g_hid_h[N_HID], g_hid_l[N_HID];
__device__ __align__(16) __nv_bfloat16 g_wt_h[N_WT],   g_wt_l[N_WT];
__device__ __align__(16) __nv_bfloat16 g_qkv_h[N_QKV], g_qkv_l[N_QKV];
__device__ __align__(16) __nv_bfloat16 g_p_h[N_P],     g_p_l[N_P];
__device__ __align__(16) __nv_bfloat16 g_vt_h[N_VT],   g_vt_l[N_VT];

// ---------------------------------------------------------------------------
// Portable primitives (sm_80+ baseline; assemble for sm_103).
// ---------------------------------------------------------------------------
__device__ __forceinline__ uint32_t smem_u32(const void* p) {
    uint32_t a;
    asm("{ .reg .u64 t; cvta.to.shared.u64 t, %1; cvt.u32.u64 %0, t; }"
        : "=r"(a) : "l"(p));
    return a;
}

__device__ __forceinline__ void ldsm_x4(uint32_t& r0, uint32_t& r1,
                                        uint32_t& r2, uint32_t& r3, uint32_t addr) {
    asm volatile("ldmatrix.sync.aligned.m8n8.x4.shared.b16 {%0,%1,%2,%3}, [%4];"
                 : "=r"(r0), "=r"(r1), "=r"(r2), "=r"(r3) : "r"(addr));
}

// D += A * B  (m16n8k16, bf16 inputs, fp32 accum)
__device__ __forceinline__ void mma_bf16(float* d, const uint32_t* a, const uint32_t* b) {
    asm volatile(
        "mma.sync.aligned.m16n8k16.row.col.f32.bf16.bf16.f32 "
        "{%0,%1,%2,%3}, {%4,%5,%6,%7}, {%8,%9}, {%0,%1,%2,%3};"
        : "+f"(d[0]), "+f"(d[1]), "+f"(d[2]), "+f"(d[3])
        : "r"(a[0]), "r"(a[1]), "r"(a[2]), "r"(a[3]), "r"(b[0]), "r"(b[1]));
}

__device__ __forceinline__ void cp_async16(uint32_t dst, const void* src) {
    asm volatile("cp.async.cg.shared.global [%0], [%1], 16;" :: "r"(dst), "l"(src));
}
#define CP_COMMIT() asm volatile("cp.async.commit_group;" ::: "memory")
#define CP_WAIT0()  asm volatile("cp.async.wait_group 0;"  ::: "memory")

// split fp32 pair into packed bf16 hi pair + bf16 lo (residual) pair
__device__ __forceinline__ void split2(float a, float b, uint32_t& hi, uint32_t& lo) {
    __nv_bfloat16 ha = __float2bfloat16(a);
    __nv_bfloat16 hb = __float2bfloat16(b);
    __nv_bfloat16 la = __float2bfloat16(a - __bfloat162float(ha));
    __nv_bfloat16 lb = __float2bfloat16(b - __bfloat162float(hb));
    __nv_bfloat162 h2 = __nv_bfloat162(ha, hb);
    __nv_bfloat162 l2 = __nv_bfloat162(la, lb);
    hi = *reinterpret_cast<uint32_t*>(&h2);
    lo = *reinterpret_cast<uint32_t*>(&l2);
}

// ---------------------------------------------------------------------------
// convert: fp32 -> (bf16 hi, bf16 lo) elementwise, vectorized x4, grid-stride.
// ---------------------------------------------------------------------------
__global__ __launch_bounds__(256) void convert_kernel(
    const float* __restrict__ src, __nv_bfloat16* __restrict__ hi,
    __nv_bfloat16* __restrict__ lo, long long n4)
{
    long long i = (long long)blockIdx.x * 256 + threadIdx.x;
    const long long stride = (long long)gridDim.x * 256;
    for (; i < n4; i += stride) {
        float4 v = reinterpret_cast<const float4*>(src)[i];
        uint32_t h0, l0, h1, l1;
        split2(v.x, v.y, h0, l0);
        split2(v.z, v.w, h1, l1);
        reinterpret_cast<uint2*>(hi)[i] = make_uint2(h0, h1);
        reinterpret_cast<uint2*>(lo)[i] = make_uint2(l0, l1);
    }
}

// ---------------------------------------------------------------------------
// bf16x3 HMMA GEMM with cp.async 2-stage pipeline.
//   C[z] = alpha * (Ah+Al)[z] (M x K, lda) * ((Bh+Bl)[z])^T  (B stored N x K)
// CTA tile 128x128, K-chunk 32. 8 warps 4(m)x2(n), warp tile 32x64.
// Terms: Ah*Bh + Ah*Bl + Al*Bh (fp32 accum).
// Dynamic smem: 2 stages x 4 tiles x 128x40 bf16 = 81920 B -> 2 CTA/SM.
// ---------------------------------------------------------------------------
#define BM 128
#define BN 128
#define BK 32
#define LDT 40                    // halves per row (80 B): conflict-free ldmatrix
#define TILE_B (BM * LDT * 2)     // 10240 B per tile
#define STAGE_B (4 * TILE_B)      // 40960 B
#define GSMEM_B (2 * STAGE_B)     // 81920 B

__global__ __launch_bounds__(256) void gemm_bf16_kernel(
    int K, float alpha,
    const __nv_bfloat16* __restrict__ AhB, const __nv_bfloat16* __restrict__ AlB,
    long long sA, int lda,
    const __nv_bfloat16* __restrict__ BhB, const __nv_bfloat16* __restrict__ BlB,
    long long sB, int ldb,
    float* __restrict__ Cbase, long long sC, int ldc)
{
    extern __shared__ char smem[];
    const uint32_t sbase = smem_u32(smem);
    const int tid  = threadIdx.x;
    const int wid  = tid >> 5;
    const int lane = tid & 31;

    const int rowBase = blockIdx.y * BM;
    const int colBase = blockIdx.x * BN;

    // per-tile global source rows (0:Ah 1:Al 2:Bh 3:Bl)
    const __nv_bfloat16* tsrc[4];
    tsrc[0] = AhB + (long long)blockIdx.z * sA + (long long)rowBase * lda;
    tsrc[1] = AlB + (long long)blockIdx.z * sA + (long long)rowBase * lda;
    tsrc[2] = BhB + (long long)blockIdx.z * sB + (long long)colBase * ldb;
    tsrc[3] = BlB + (long long)blockIdx.z * sB + (long long)colBase * ldb;
    float* C = Cbase + (long long)blockIdx.z * sC;

    const int warpM = wid & 3;
    const int warpN = wid >> 2;
    const int wRow  = warpM * 32;
    const int wCol  = warpN * 64;

    float acc[2][8][4];
    #pragma unroll
    for (int i = 0; i < 2; i++)
        #pragma unroll
        for (int j = 0; j < 8; j++)
            #pragma unroll
            for (int q = 0; q < 4; q++) acc[i][j][q] = 0.0f;

    // ldmatrix lane addressing (half-element indices)
    const int aLRow = lane & 15;
    const int aLCol = (lane >> 4) * 8;
    const int bLRow = ((lane >> 4) ? 8 : 0) + (lane & 7);
    const int bLCol = ((lane >> 3) & 1) * 8;

    // fill one stage: 2048 x 16B cp.async chunks, 8 per thread.
    // For fixed it, tile id t = (tid + it*256) >> 9 = it >> 1 (uniform).
    auto issue_fill = [&](int k0, int st) {
        #pragma unroll
        for (int it = 0; it < 8; it++) {
            const int idx = tid + it * 256;
            const int t   = it >> 1;                 // tile id (uniform)
            const int r   = (idx >> 2) & 127;        // row in tile
            const int c8  = (idx & 3) * 8;           // col elems (16 B)
            const int ld  = (t < 2) ? lda : ldb;
            const __nv_bfloat16* src = tsrc[t] + (long long)r * ld + k0 + c8;
            const uint32_t dst = sbase + st * STAGE_B + t * TILE_B
                               + r * (LDT * 2) + (idx & 3) * 16;
            cp_async16(dst, src);
        }
        CP_COMMIT();
    };

    issue_fill(0, 0);
    const int nch = K / BK;
    int buf = 0;

    for (int c = 0; c < nch; c++) {
        CP_WAIT0();
        __syncthreads();          // stage `buf` visible; prior compute done
        if (c + 1 < nch) issue_fill((c + 1) * BK, buf ^ 1);

        const uint32_t cAh = sbase + buf * STAGE_B;
        const uint32_t cAl = cAh + TILE_B;
        const uint32_t cBh = cAl + TILE_B;
        const uint32_t cBl = cBh + TILE_B;

        #pragma unroll
        for (int ks = 0; ks < 2; ks++) {
            const int kk = ks * 16;

            uint32_t ah[2][4], al[2][4];
            #pragma unroll
            for (int mi = 0; mi < 2; mi++) {
                const uint32_t off =
                    (uint32_t)((wRow + mi * 16 + aLRow) * LDT + kk + aLCol) * 2u;
                ldsm_x4(ah[mi][0], ah[mi][1], ah[mi][2], ah[mi][3], cAh + off);
                ldsm_x4(al[mi][0], al[mi][1], al[mi][2], al[mi][3], cAl + off);
            }

            uint32_t bh[8][2], bl[8][2];
            #pragma unroll
            for (int pi = 0; pi < 4; pi++) {
                const uint32_t off =
                    (uint32_t)((wCol + pi * 16 + bLRow) * LDT + kk + bLCol) * 2u;
                ldsm_x4(bh[2*pi][0], bh[2*pi][1], bh[2*pi+1][0], bh[2*pi+1][1],
                        cBh + off);
                ldsm_x4(bl[2*pi][0], bl[2*pi][1], bl[2*pi+1][0], bl[2*pi+1][1],
                        cBl + off);
            }

            #pragma unroll
            for (int mi = 0; mi < 2; mi++)
                #pragma unroll
                for (int ni = 0; ni < 8; ni++) {
                    mma_bf16(acc[mi][ni], ah[mi], bh[ni]);   // hi*hi
                    mma_bf16(acc[mi][ni], ah[mi], bl[ni]);   // hi*lo
                    mma_bf16(acc[mi][ni], al[mi], bh[ni]);   // lo*hi
                }
        }
        buf ^= 1;
    }

    // epilogue: C = alpha * acc
    const int fRow = lane >> 2;
    const int fCol = (lane & 3) * 2;
    #pragma unroll
    for (int mi = 0; mi < 2; mi++) {
        #pragma unroll
        for (int ni = 0; ni < 8; ni++) {
            const long long r0 = rowBase + wRow + mi * 16 + fRow;
            const int c = colBase + wCol + ni * 8 + fCol;
            float2 v0 = make_float2(alpha * acc[mi][ni][0], alpha * acc[mi][ni][1]);
            float2 v1 = make_float2(alpha * acc[mi][ni][2], alpha * acc[mi][ni][3]);
            *reinterpret_cast<float2*>(C + r0 * ldc + c)       = v0;
            *reinterpret_cast<float2*>(C + (r0 + 8) * ldc + c) = v1;
        }
    }
}

// ---------------------------------------------------------------------------
// fp32 tiled transpose: out[x][y] = in[y][x], 32x32 tiles, block (32,8).
// ---------------------------------------------------------------------------
__global__ __launch_bounds__(256) void transpose_kernel(
    const float* __restrict__ in, float* __restrict__ out,
    int ldi, int ldo, long long sIn, long long sOut)
{
    __shared__ float tile[32][33];
    const float* ip = in + (long long)blockIdx.z * sIn;
    float*       op = out + (long long)blockIdx.z * sOut;
    int x  = blockIdx.x * 32 + threadIdx.x;
    int y0 = blockIdx.y * 32 + threadIdx.y;
    #pragma unroll
    for (int i = 0; i < 32; i += 8)
        tile[threadIdx.y + i][threadIdx.x] = ip[(long long)(y0 + i) * ldi + x];
    __syncthreads();
    int ox  = blockIdx.y * 32 + threadIdx.x;
    int oy0 = blockIdx.x * 32 + threadIdx.y;
    #pragma unroll
    for (int i = 0; i < 32; i += 8)
        op[(long long)(oy0 + i) * ldo + ox] = tile[threadIdx.x][threadIdx.y + i];
}

// ---------------------------------------------------------------------------
// Row softmax over P (in place, fp32): one block per row, 2048 cols.
// ---------------------------------------------------------------------------
__inline__ __device__ float warpReduceMax(float v) {
    #pragma unroll
    for (int o = 16; o > 0; o >>= 1) v = fmaxf(v, __shfl_xor_sync(0xFFFFFFFFu, v, o));
    return v;
}
__inline__ __device__ float warpReduceSum(float v) {
    #pragma unroll
    for (int o = 16; o > 0; o >>= 1) v += __shfl_xor_sync(0xFFFFFFFFu, v, o);
    return v;
}

__global__ __launch_bounds__(256) void softmax_rows_kernel(float* __restrict__ P, int cols)
{
    float* p = P + (long long)blockIdx.x * cols;
    const int tid = threadIdx.x, lane = tid & 31, warp = tid >> 5;
    __shared__ float red[8];
    __shared__ float s_stat;

    float4 v0 = reinterpret_cast<const float4*>(p)[tid];
    float4 v1 = reinterpret_cast<const float4*>(p)[tid + 256];

    float m = fmaxf(fmaxf(fmaxf(v0.x, v0.y), fmaxf(v0.z, v0.w)),
                    fmaxf(fmaxf(v1.x, v1.y), fmaxf(v1.z, v1.w)));
    m = warpReduceMax(m);
    if (lane == 0) red[warp] = m;
    __syncthreads();
    if (warp == 0) {
        float t = (lane < 8) ? red[lane] : -CUDART_INF_F;
        t = warpReduceMax(t);
        if (lane == 0) s_stat = t;
    }
    __syncthreads();
    const float rmax = s_stat;

    v0.x = __expf(v0.x - rmax); v0.y = __expf(v0.y - rmax);
    v0.z = __expf(v0.z - rmax); v0.w = __expf(v0.w - rmax);
    v1.x = __expf(v1.x - rmax); v1.y = __expf(v1.y - rmax);
    v1.z = __expf(v1.z - rmax); v1.w = __expf(v1.w - rmax);
    float s = (v0.x + v0.y + v0.z + v0.w) + (v1.x + v1.y + v1.z + v1.w);
    s = warpReduceSum(s);
    if (lane == 0) red[warp] = s;
    __syncthreads();
    if (warp == 0) {
        float t = (lane < 8) ? red[lane] : 0.0f;
        t = warpReduceSum(t);
        if (lane == 0) s_stat = t;
    }
    __syncthreads();
    const float inv = __frcp_rn(s_stat);

    v0.x *= inv; v0.y *= inv; v0.z *= inv; v0.w *= inv;
    v1.x *= inv; v1.y *= inv; v1.z *= inv; v1.w *= inv;
    reinterpret_cast<float4*>(p)[tid]       = v0;
    reinterpret_cast<float4*>(p)[tid + 256] = v1;
}

// ---------------------------------------------------------------------------
// kernel_launch
// ---------------------------------------------------------------------------
extern "C" void kernel_launch(void* const* d_in, const int* in_sizes, int n_in,
                              void* d_out, int out_size)
{
    const float* hidden = (const float*)d_in[0];   // [B,S,E]
    const float* W      = (const float*)d_in[1];   // [E,3E]
    float*       out    = (float*)d_out;           // [B,S,E]

    static float *qkv = nullptr, *P = nullptr, *Wt = nullptr, *Vt = nullptr;
    static __nv_bfloat16 *hid_h, *hid_l, *wt_h, *wt_l, *qkv_h, *qkv_l,
                         *p_h, *p_l, *vt_h, *vt_l;
    static bool inited = false;
    if (!inited) {
        cudaGetSymbolAddress((void**)&qkv,   g_qkv);
        cudaGetSymbolAddress((void**)&P,     g_p);
        cudaGetSymbolAddress((void**)&Wt,    g_wt);
        cudaGetSymbolAddress((void**)&Vt,    g_vt);
        cudaGetSymbolAddress((void**)&hid_h, g_hid_h);
        cudaGetSymbolAddress((void**)&hid_l, g_hid_l);
        cudaGetSymbolAddress((void**)&wt_h,  g_wt_h);
        cudaGetSymbolAddress((void**)&wt_l,  g_wt_l);
        cudaGetSymbolAddress((void**)&qkv_h, g_qkv_h);
        cudaGetSymbolAddress((void**)&qkv_l, g_qkv_l);
        cudaGetSymbolAddress((void**)&p_h,   g_p_h);
        cudaGetSymbolAddress((void**)&p_l,   g_p_l);
        cudaGetSymbolAddress((void**)&vt_h,  g_vt_h);
        cudaGetSymbolAddress((void**)&vt_l,  g_vt_l);
        cudaFuncSetAttribute(gemm_bf16_kernel,
                             cudaFuncAttributeMaxDynamicSharedMemorySize, GSMEM_B);
        inited = true;
    }

    const int E3 = 3 * EMBED;
    dim3 tb(32, 8);
    const int CVG = 4096;   // convert grid (grid-stride handles remainder)

    // 1) Wt = W^T (fp32), then split
    transpose_kernel<<<dim3(E3 / 32, EMBED / 32, 1), tb>>>(W, Wt, E3, EMBED, 0, 0);
    convert_kernel<<<CVG, 256>>>(Wt, wt_h, wt_l, N_WT / 4);

    // 2) split hidden
    convert_kernel<<<CVG, 256>>>(hidden, hid_h, hid_l, N_HID / 4);

    // 3) qkv = hidden @ W
    gemm_bf16_kernel<<<dim3(E3 / BN, (NBATCH * SEQ) / BM, 1), 256, GSMEM_B>>>(
        EMBED, 1.0f,
        hid_h, hid_l, 0, EMBED,
        wt_h,  wt_l,  0, EMBED,
        qkv, 0, E3);

    // 4) split qkv (Q,K consumed by scores GEMM)
    convert_kernel<<<CVG, 256>>>(qkv, qkv_h, qkv_l, N_QKV / 4);

    // 5) Vt = V^T (fp32), then split
    transpose_kernel<<<dim3(EMBED / 32, SEQ / 32, NBATCH), tb>>>(
        qkv + 2 * EMBED, Vt, E3, SEQ,
        (long long)SEQ * E3, (long long)EMBED * SEQ);
    convert_kernel<<<CVG, 256>>>(Vt, vt_h, vt_l, N_VT / 4);

    // 6) P = (Q @ K^T) / 32
    gemm_bf16_kernel<<<dim3(SEQ / BN, SEQ / BM, NBATCH), 256, GSMEM_B>>>(
        EMBED, 1.0f / 32.0f,
        qkv_h,         qkv_l,         (long long)SEQ * E3, E3,
        qkv_h + EMBED, qkv_l + EMBED, (long long)SEQ * E3, E3,
        P, (long long)SEQ * SEQ, SEQ);

    // 7) softmax rows, then split P
    softmax_rows_kernel<<<NBATCH * SEQ, 256>>>(P, SEQ);
    convert_kernel<<<CVG, 256>>>(P, p_h, p_l, N_P / 4);

    // 8) out = P @ V = P @ Vt^T
    gemm_bf16_kernel<<<dim3(EMBED / BN, SEQ / BM, NBATCH), 256, GSMEM_B>>>(
        SEQ, 1.0f,
        p_h,  p_l,  (long long)SEQ * SEQ,   SEQ,
        vt_h, vt_l, (long long)EMBED * SEQ, SEQ,
        out, (long long)SEQ * EMBED, EMBED);
}